// round 1
// baseline (speedup 1.0000x reference)
#include <cuda_runtime.h>
#include <cstddef>

#define BB      65536
#define DMODEL  2048
#define NE      64
#define TOPK    8
#define ROWS    128          // rows per CTA
#define KC      64           // K tile
#define NCTA    (BB / ROWS)  // 512
#define LSP     65           // padded pitch for x-tile / logits tile
#define NTHREADS 256

// Deterministic per-CTA partials for the aux loss (no atomics).
__device__ float g_partP[NCTA * NE];
__device__ float g_partC[NCTA * NE];

// Dynamic smem layout (floats):
//  [0, 8320)            xs[128][65]   (mainloop)  == ls[128][65] (epilogue logits)
//  [8320, 16512)        ws[64][64]    (mainloop)  \__ pb[128][64] spans [8320,16512)
//  [8320, 16512)        pb low half              /   (pb = probs, then gates buffer)
//  [16512, 16576)       eb[64]        expert bias
//  [16576, 16832)       red[256]      reduction scratch
#define SMEM_FLOATS (ROWS*LSP + ROWS*NE + NE + NTHREADS)
#define SMEM_BYTES  (SMEM_FLOATS * 4)

__global__ void __launch_bounds__(NTHREADS)
router_kernel(const float* __restrict__ x,
              const float* __restrict__ Wm,
              const float* __restrict__ eb_g,
              float* __restrict__ out)
{
    extern __shared__ float sm[];
    float* xs  = sm;                       // [128][65]
    float* ws  = sm + ROWS * LSP;          // [64][64]
    float* ls  = sm;                       // reuse of xs
    float* pb  = sm + ROWS * LSP;          // [128][64], reuse of ws + beyond
    float* eb  = sm + ROWS * LSP + ROWS * NE;
    float* red = eb + NE;

    const int tid = threadIdx.x;
    const int r0  = blockIdx.x * ROWS;
    const int tx  = tid & 15;   // col group: cols [tx*4, tx*4+4)
    const int ty  = tid >> 4;   // row group: rows [ty*8, ty*8+8)

    if (tid < NE) eb[tid] = eb_g[tid];

    float acc[8][4];
#pragma unroll
    for (int i = 0; i < 8; i++)
#pragma unroll
        for (int j = 0; j < 4; j++) acc[i][j] = 0.f;

    // ---------------- mainloop: logits tile = x_tile @ W_tile ----------------
    for (int k0 = 0; k0 < DMODEL; k0 += KC) {
        // fill xs: 128 rows x 64 k  (2048 float4, 8 per thread)
#pragma unroll
        for (int it = 0; it < 8; ++it) {
            int id  = it * NTHREADS + tid;   // 0..2047
            int row = id >> 4;
            int q   = id & 15;
            const float4 v = *reinterpret_cast<const float4*>(
                x + (size_t)(r0 + row) * DMODEL + k0 + q * 4);
            float* dst = &xs[row * LSP + q * 4];
            dst[0] = v.x; dst[1] = v.y; dst[2] = v.z; dst[3] = v.w;
        }
        // fill ws: 64 k x 64 experts (1024 float4, 4 per thread)
#pragma unroll
        for (int it = 0; it < 4; ++it) {
            int id = it * NTHREADS + tid;    // 0..1023
            int kr = id >> 4;
            int q  = id & 15;
            const float4 v = *reinterpret_cast<const float4*>(
                Wm + (size_t)(k0 + kr) * NE + q * 4);
            *reinterpret_cast<float4*>(&ws[kr * NE + q * 4]) = v;
        }
        __syncthreads();

#pragma unroll 8
        for (int kk = 0; kk < KC; ++kk) {
            const float4 bv = *reinterpret_cast<const float4*>(&ws[kk * NE + tx * 4]);
            float a[8];
#pragma unroll
            for (int i = 0; i < 8; i++) a[i] = xs[(ty * 8 + i) * LSP + kk];
#pragma unroll
            for (int i = 0; i < 8; i++) {
                acc[i][0] += a[i] * bv.x;
                acc[i][1] += a[i] * bv.y;
                acc[i][2] += a[i] * bv.z;
                acc[i][3] += a[i] * bv.w;
            }
        }
        __syncthreads();
    }

    // ---------------- epilogue ----------------
    // store logits into ls (reuses xs region; safe: trailing sync above)
#pragma unroll
    for (int i = 0; i < 8; i++)
#pragma unroll
        for (int j = 0; j < 4; j++)
            ls[(ty * 8 + i) * LSP + tx * 4 + j] = acc[i][j];
    __syncthreads();

    // full softmax over UNbiased logits -> pb (for P_i)
    if (tid < ROWS) {
        const float* row = &ls[tid * LSP];
        float m = -1e30f;
        for (int e = 0; e < NE; e++) m = fmaxf(m, row[e]);
        float s = 0.f;
        for (int e = 0; e < NE; e++) {
            float ex = __expf(row[e] - m);
            pb[tid * NE + e] = ex;
            s += ex;
        }
        float inv = 1.0f / s;
        for (int e = 0; e < NE; e++) pb[tid * NE + e] *= inv;
    }
    __syncthreads();

    // deterministic column-reduce of P over the 128 rows
    {
        int e = tid & 63, part = tid >> 6;
        float s = 0.f;
        int rbase = part * 32;
        for (int rr = 0; rr < 32; ++rr) s += pb[(rbase + rr) * NE + e];
        red[tid] = s;
    }
    __syncthreads();
    if (tid < NE)
        g_partP[blockIdx.x * NE + tid] =
            red[tid] + red[NE + tid] + red[2 * NE + tid] + red[3 * NE + tid];
    __syncthreads();

    // biased top-8 (strict > scan => lower index wins ties, matches lax.top_k),
    // softmax over UNbiased selected logits, scatter gates into pb, write indices.
    if (tid < ROWS) {
        float* row = &ls[tid * LSP];
        int   idx[TOPK];
        float gv[TOPK];
        for (int sct = 0; sct < TOPK; ++sct) {
            float best = -1e30f; int bi = 0;
            for (int e = 0; e < NE; e++) {
                float v = row[e] + eb[e];
                if (v > best) { best = v; bi = e; }
            }
            idx[sct] = bi;
            gv[sct]  = best - eb[bi];   // unbiased logit of selected expert
            row[bi]  = -1e30f;          // mask
        }
        float m8 = gv[0];
        for (int sct = 1; sct < TOPK; ++sct) m8 = fmaxf(m8, gv[sct]);
        float ssum = 0.f;
        for (int sct = 0; sct < TOPK; ++sct) { gv[sct] = __expf(gv[sct] - m8); ssum += gv[sct]; }
        float inv = 1.0f / ssum;

        // zero this row's gates buffer, then scatter
        float4 z = make_float4(0.f, 0.f, 0.f, 0.f);
        float4* prow4 = reinterpret_cast<float4*>(&pb[tid * NE]);
        for (int q = 0; q < NE / 4; q++) prow4[q] = z;
        for (int sct = 0; sct < TOPK; ++sct) pb[tid * NE + idx[sct]] = gv[sct] * inv;

        // indices (as float) -> out[B*NE + row*8 ...]
        float* iout = out + (size_t)BB * NE + (size_t)(r0 + tid) * TOPK;
        for (int sct = 0; sct < TOPK; ++sct) iout[sct] = (float)idx[sct];
    }
    __syncthreads();

    // deterministic column-reduce of counts (gate > 0)
    {
        int e = tid & 63, part = tid >> 6;
        float s = 0.f;
        int rbase = part * 32;
        for (int rr = 0; rr < 32; ++rr) s += (pb[(rbase + rr) * NE + e] > 0.f) ? 1.f : 0.f;
        red[tid] = s;
    }
    __syncthreads();
    if (tid < NE)
        g_partC[blockIdx.x * NE + tid] =
            red[tid] + red[NE + tid] + red[2 * NE + tid] + red[3 * NE + tid];

    // coalesced store of the 128x64 gates block
    {
        const float4* src = reinterpret_cast<const float4*>(pb);
        float4* dst = reinterpret_cast<float4*>(out) + (size_t)r0 * (NE / 4);
        for (int i = tid; i < ROWS * NE / 4; i += NTHREADS) dst[i] = src[i];
    }
}

__global__ void aux_kernel(float* __restrict__ out)
{
    __shared__ float sv[NE];
    int e = threadIdx.x;  // 64 threads
    float c = 0.f, p = 0.f;
#pragma unroll 4
    for (int b = 0; b < NCTA; b++) {
        c += g_partC[b * NE + e];
        p += g_partP[b * NE + e];
    }
    sv[e] = (c * (1.0f / BB)) * (p * (1.0f / BB));
    __syncthreads();
    if (e == 0) {
        float s = 0.f;
        for (int i = 0; i < NE; i++) s += sv[i];
        out[(size_t)BB * NE + (size_t)BB * TOPK] = 0.01f * (float)NE * s;
    }
}

extern "C" void kernel_launch(void* const* d_in, const int* in_sizes, int n_in,
                              void* d_out, int out_size)
{
    const float* x   = (const float*)d_in[0];   // (B, D)
    const float* Wm  = (const float*)d_in[1];   // (D, NE)
    const float* ebg = (const float*)d_in[2];   // (NE,)
    float* out = (float*)d_out;                 // gates | indices | aux

    cudaFuncSetAttribute(router_kernel,
                         cudaFuncAttributeMaxDynamicSharedMemorySize, SMEM_BYTES);
    router_kernel<<<NCTA, NTHREADS, SMEM_BYTES>>>(x, Wm, ebg, out);
    aux_kernel<<<1, NE>>>(out);
}

// round 2
// speedup vs baseline: 1.2253x; 1.2253x over previous
#include <cuda_runtime.h>
#include <cstdint>
#include <cstddef>

#define BB      65536
#define DMODEL  2048
#define NE      64
#define TOPK    8
#define ROWS    128            // rows per CTA
#define KC      32             // K per stage
#define NSTAGE  (DMODEL / KC)  // 64
#define NCTA    (BB / ROWS)    // 512
#define NTHREADS 128
#define LSP     65             // padded pitch for epilogue logits

// deterministic per-CTA partials for aux loss
__device__ float g_partP[NCTA * NE];
__device__ float g_partC[NCTA * NE];

// ---- smem layout (float offsets) ----
// mainloop: XS0[128*32] XS1[128*32] WS0[32*64] WS1[32*64]  -> 12288 floats
// epilogue: LS[128*65]=8320 @0 (reuses XS*), GB[128*64]=8192 @8320 (reuses WS*+)
// tail (disjoint from both): EB, RMAX, RINV, RED, SCNT
#define OFF_XS0 0
#define OFF_XS1 4096
#define OFF_WS0 8192
#define OFF_WS1 10240
#define OFF_LS  0
#define OFF_GB  8320
#define OFF_EB  16512
#define OFF_RMAX 16576
#define OFF_RINV 16704
#define OFF_RED 16832
#define OFF_SCNT 16960
#define SMEM_FLOATS 17024
#define SMEM_BYTES (SMEM_FLOATS * 4)

__device__ __forceinline__ void cp16(uint32_t dst_s, const void* src) {
    asm volatile("cp.async.cg.shared.global [%0], [%1], 16;" :: "r"(dst_s), "l"(src));
}
__device__ __forceinline__ void cp_commit() {
    asm volatile("cp.async.commit_group;");
}
template<int N>
__device__ __forceinline__ void cp_wait() {
    asm volatile("cp.async.wait_group %0;" :: "n"(N));
}

#define FMA2(acc, a2, b2) \
    asm("fma.rn.f32x2 %0, %1, %2, %0;" : "+l"(acc) : "l"(a2), "l"(b2))

// issue one stage of loads: x tile 128x32 (swizzled), W tile 32x64
__device__ __forceinline__ void stage_load(const float* __restrict__ x,
                                           const float* __restrict__ Wm,
                                           int r0, int k0,
                                           uint32_t xs_s, uint32_t ws_s, int tid)
{
#pragma unroll
    for (int q = 0; q < 8; q++) {            // 1024 float4 for x tile
        int id  = q * NTHREADS + tid;
        int row = id >> 3;
        int c4  = id & 7;
        int col = (c4 * 4) ^ (((row >> 3) & 3) << 3);   // XOR swizzle (16B-preserving)
        cp16(xs_s + (uint32_t)(row * KC + col) * 4,
             x + (size_t)(r0 + row) * DMODEL + k0 + c4 * 4);
    }
#pragma unroll
    for (int q = 0; q < 4; q++) {            // 512 float4 for W tile
        int id = q * NTHREADS + tid;
        int kr = id >> 4;
        int c4 = id & 15;
        cp16(ws_s + (uint32_t)(kr * NE + c4 * 4) * 4,
             Wm + (size_t)(k0 + kr) * NE + c4 * 4);
    }
    cp_commit();
}

__global__ void __launch_bounds__(NTHREADS)
router_kernel(const float* __restrict__ x,
              const float* __restrict__ Wm,
              const float* __restrict__ eb_g,
              float* __restrict__ out)
{
    extern __shared__ float sm[];
    float* ls   = sm + OFF_LS;
    float* gb   = sm + OFF_GB;
    float* eb   = sm + OFF_EB;
    float* rmax = sm + OFF_RMAX;
    float* rinv = sm + OFF_RINV;
    float* red  = sm + OFF_RED;
    int*   scnt = (int*)(sm + OFF_SCNT);

    uint32_t smem_u32;
    asm("{ .reg .u64 t; cvta.to.shared.u64 t, %1; cvt.u32.u64 %0, t; }"
        : "=r"(smem_u32) : "l"(sm));
    const uint32_t xs_s[2] = { smem_u32 + OFF_XS0 * 4, smem_u32 + OFF_XS1 * 4 };
    const uint32_t ws_s[2] = { smem_u32 + OFF_WS0 * 4, smem_u32 + OFF_WS1 * 4 };
    const float* xs_f[2] = { sm + OFF_XS0, sm + OFF_XS1 };
    const float* ws_f[2] = { sm + OFF_WS0, sm + OFF_WS1 };

    const int tid = threadIdx.x;
    const int r0  = blockIdx.x * ROWS;
    const int tx  = tid & 7;          // 8 expert groups
    const int ty  = tid >> 3;         // 16 row groups of 8
    const int sw  = (ty & 3) << 3;    // A-read swizzle for this thread's rows

    if (tid < NE) eb[tid] = eb_g[tid];
    if (tid < NE) scnt[tid] = 0;

    unsigned long long acc[8][4];
#pragma unroll
    for (int i = 0; i < 8; i++)
#pragma unroll
        for (int p = 0; p < 4; p++) acc[i][p] = 0ULL;

    // ---------------- pipelined mainloop ----------------
    stage_load(x, Wm, r0, 0, xs_s[0], ws_s[0], tid);

    for (int st = 0; st < NSTAGE; st++) {
        if (st + 1 < NSTAGE) {
            stage_load(x, Wm, r0, (st + 1) * KC, xs_s[(st + 1) & 1], ws_s[(st + 1) & 1], tid);
            cp_wait<1>();
        } else {
            cp_wait<0>();
        }
        __syncthreads();

        const float* xs = xs_f[st & 1];
        const float* ws = ws_f[st & 1];
        const float* xrow_base = xs + ty * 8 * KC;

#pragma unroll 8
        for (int kk = 0; kk < KC; kk++) {
            // B frag: experts {4tx..4tx+3} and {32+4tx..32+4tx+3} as packed f32x2 pairs
            ulonglong2 bA = *reinterpret_cast<const ulonglong2*>(ws + kk * NE + tx * 4);
            ulonglong2 bB = *reinterpret_cast<const ulonglong2*>(ws + kk * NE + 32 + tx * 4);
            int kcol = kk ^ sw;
#pragma unroll
            for (int i = 0; i < 8; i++) {
                float a = xrow_base[i * KC + kcol];
                unsigned long long aa;
                asm("mov.b64 %0, {%1, %1};" : "=l"(aa) : "r"(__float_as_uint(a)));
                FMA2(acc[i][0], aa, bA.x);
                FMA2(acc[i][1], aa, bA.y);
                FMA2(acc[i][2], aa, bB.x);
                FMA2(acc[i][3], aa, bB.y);
            }
        }
        __syncthreads();
    }

    // ---------------- epilogue ----------------
    // write logits to ls[128][65]
#pragma unroll
    for (int i = 0; i < 8; i++) {
        int r = ty * 8 + i;
#pragma unroll
        for (int p = 0; p < 4; p++) {
            float2 v = *reinterpret_cast<float2*>(&acc[i][p]);
            int e0 = (p < 2) ? (4 * tx + 2 * p) : (32 + 4 * tx + 2 * (p - 2));
            ls[r * LSP + e0]     = v.x;
            ls[r * LSP + e0 + 1] = v.y;
        }
    }
    __syncthreads();

    // row pass: max and 1/sum(exp) per row (unbiased logits)
    {
        const float* row = &ls[tid * LSP];
        float m = row[0];
#pragma unroll 8
        for (int e = 1; e < NE; e++) m = fmaxf(m, row[e]);
        float s = 0.f;
#pragma unroll 8
        for (int e = 0; e < NE; e++) s += __expf(row[e] - m);
        rmax[tid] = m;
        rinv[tid] = 1.0f / s;
    }
    __syncthreads();

    // column pass: deterministic P_i partial sums (recompute exp)
    {
        int e = tid & 63, half = tid >> 6;
        float s = 0.f;
        int rb = half * 64;
#pragma unroll 8
        for (int rr = 0; rr < 64; rr++) {
            int r = rb + rr;
            s += __expf(ls[r * LSP + e] - rmax[r]) * rinv[r];
        }
        red[tid] = s;
    }
    __syncthreads();
    if (tid < NE) g_partP[blockIdx.x * NE + tid] = red[tid] + red[NE + tid];
    __syncthreads();

    // top-8 per row (biased, strict > => lower index wins ties), selected softmax,
    // scatter gates into gb, histogram counts, write indices.
    {
        float* row = &ls[tid * LSP];
        int   idx[TOPK];
        float gv[TOPK];
        for (int sct = 0; sct < TOPK; ++sct) {
            float best = -1e30f; int bi = 0;
#pragma unroll 8
            for (int e = 0; e < NE; e++) {
                float v = row[e] + eb[e];
                if (v > best) { best = v; bi = e; }
            }
            idx[sct] = bi;
            gv[sct]  = best - eb[bi];
            row[bi]  = -1e30f;
        }
        float m8 = gv[0];
#pragma unroll
        for (int sct = 1; sct < TOPK; ++sct) m8 = fmaxf(m8, gv[sct]);
        float ssum = 0.f;
#pragma unroll
        for (int sct = 0; sct < TOPK; ++sct) { gv[sct] = __expf(gv[sct] - m8); ssum += gv[sct]; }
        float inv = 1.0f / ssum;

        float4 z = make_float4(0.f, 0.f, 0.f, 0.f);
        float4* grow = reinterpret_cast<float4*>(&gb[tid * NE]);
#pragma unroll
        for (int q = 0; q < NE / 4; q++) grow[q] = z;
#pragma unroll
        for (int sct = 0; sct < TOPK; ++sct) {
            gb[tid * NE + idx[sct]] = gv[sct] * inv;
            atomicAdd(&scnt[idx[sct]], 1);
        }

        float* iout = out + (size_t)BB * NE + (size_t)(r0 + tid) * TOPK;
#pragma unroll
        for (int sct = 0; sct < TOPK; ++sct) iout[sct] = (float)idx[sct];
    }
    __syncthreads();

    if (tid < NE) g_partC[blockIdx.x * NE + tid] = (float)scnt[tid];

    // coalesced store of the 128x64 gates block
    {
        const float4* src = reinterpret_cast<const float4*>(gb);
        float4* dst = reinterpret_cast<float4*>(out) + (size_t)r0 * (NE / 4);
#pragma unroll
        for (int q = 0; q < (ROWS * NE / 4) / NTHREADS; q++)
            dst[q * NTHREADS + tid] = src[q * NTHREADS + tid];
    }
}

__global__ void __launch_bounds__(1024)
aux_kernel(float* __restrict__ out)
{
    __shared__ float sc[1024], sp[1024], sv[NE];
    int t = threadIdx.x;
    int e = t & 63, ch = t >> 6;          // 16 chunks of 32 CTAs
    float c = 0.f, p = 0.f;
#pragma unroll 4
    for (int b = ch * 32; b < ch * 32 + 32; ++b) {
        c += g_partC[b * NE + e];
        p += g_partP[b * NE + e];
    }
    sc[t] = c; sp[t] = p;
    __syncthreads();
    if (t < NE) {
        float cc = 0.f, pp = 0.f;
#pragma unroll
        for (int k = 0; k < 16; k++) { cc += sc[k * 64 + e]; pp += sp[k * 64 + e]; }
        sv[e] = (cc * (1.0f / BB)) * (pp * (1.0f / BB));
    }
    __syncthreads();
    if (t == 0) {
        float s = 0.f;
#pragma unroll
        for (int i = 0; i < NE; i++) s += sv[i];
        out[(size_t)BB * NE + (size_t)BB * TOPK] = 0.01f * (float)NE * s;
    }
}

extern "C" void kernel_launch(void* const* d_in, const int* in_sizes, int n_in,
                              void* d_out, int out_size)
{
    const float* x   = (const float*)d_in[0];   // (B, D)
    const float* Wm  = (const float*)d_in[1];   // (D, NE)
    const float* ebg = (const float*)d_in[2];   // (NE,)
    float* out = (float*)d_out;                 // gates | indices | aux

    cudaFuncSetAttribute(router_kernel,
                         cudaFuncAttributeMaxDynamicSharedMemorySize, SMEM_BYTES);
    router_kernel<<<NCTA, NTHREADS, SMEM_BYTES>>>(x, Wm, ebg, out);
    aux_kernel<<<1, 1024>>>(out);
}